// round 2
// baseline (speedup 1.0000x reference)
#include <cuda_runtime.h>
#include <cmath>
#include <cstdint>

#define D_MODEL 1024
#define D_FF    4096
#define NEXP    8
#define TOKENS  4096            // B*S = 2*2048
#define NASSIGN (TOKENS * 2)    // top-k = 2

// ---------------- device scratch (no allocations allowed) ----------------
__device__ int   g_cnt[NEXP];
__device__ int   g_off[NEXP + 1];
__device__ int   g_perm[NASSIGN];          // token index per assignment slot
__device__ float g_wt[NASSIGN];            // renormalized gate weight per slot
__device__ float g_probs[TOKENS * NEXP];   // softmax probs (for aux loss)
__device__ int   g_argmax[TOKENS];
__device__ int   g_tkidx[TOKENS * 2];
__device__ float g_tkw[TOKENS * 2];
__device__ __align__(16) float g_h[(size_t)NASSIGN * D_FF];  // 134 MB intermediate

// ---------------- helpers ----------------
__device__ __forceinline__ unsigned long long pack2(float v) {
    unsigned long long r;
    asm("mov.b64 %0, {%1, %1};" : "=l"(r) : "f"(v));
    return r;
}
__device__ __forceinline__ void fma2(unsigned long long& d, unsigned long long a,
                                     unsigned long long b) {
    asm("fma.rn.f32x2 %0, %1, %2, %0;" : "+l"(d) : "l"(a), "l"(b));
}
__device__ __forceinline__ float2 unpack2(unsigned long long v) {
    float2 f;
    asm("mov.b64 {%0, %1}, %2;" : "=f"(f.x), "=f"(f.y) : "l"(v));
    return f;
}
__device__ __forceinline__ float gelu_exact(float v) {
    return 0.5f * v * (1.0f + erff(v * 0.70710678118654752f));
}

// ---------------- router: logits -> softmax -> top2 -> renorm ----------------
__global__ void router_kernel(const float* __restrict__ x,
                              const float* __restrict__ Wr,
                              const float* __restrict__ br) {
    const int t = blockIdx.x;
    const float* xr = x + (size_t)t * D_MODEL;
    float acc[NEXP];
    #pragma unroll
    for (int e = 0; e < NEXP; e++) acc[e] = 0.f;
    for (int d = threadIdx.x; d < D_MODEL; d += 128) {
        float xv = xr[d];
        const float* w = Wr + d * NEXP;
        #pragma unroll
        for (int e = 0; e < NEXP; e++) acc[e] = fmaf(xv, w[e], acc[e]);
    }
    __shared__ float red[NEXP][128];
    #pragma unroll
    for (int e = 0; e < NEXP; e++) red[e][threadIdx.x] = acc[e];
    __syncthreads();
    for (int s = 64; s > 0; s >>= 1) {
        if (threadIdx.x < s) {
            #pragma unroll
            for (int e = 0; e < NEXP; e++)
                red[e][threadIdx.x] += red[e][threadIdx.x + s];
        }
        __syncthreads();
    }
    if (threadIdx.x == 0) {
        float lg[NEXP], p[NEXP];
        float mx = -1e30f;
        #pragma unroll
        for (int e = 0; e < NEXP; e++) { lg[e] = red[e][0] + br[e]; mx = fmaxf(mx, lg[e]); }
        float s = 0.f;
        #pragma unroll
        for (int e = 0; e < NEXP; e++) { p[e] = expf(lg[e] - mx); s += p[e]; }
        float inv = 1.f / s;
        #pragma unroll
        for (int e = 0; e < NEXP; e++) { p[e] *= inv; g_probs[t * NEXP + e] = p[e]; }
        int i1 = 0;
        #pragma unroll
        for (int e = 1; e < NEXP; e++) if (p[e] > p[i1]) i1 = e;
        int i2 = (i1 == 0) ? 1 : 0;
        #pragma unroll
        for (int e = 0; e < NEXP; e++) if (e != i1 && p[e] > p[i2]) i2 = e;
        float v1 = p[i1], v2 = p[i2];
        float sum = fmaxf(v1 + v2, 1e-9f);
        g_tkidx[2 * t] = i1;  g_tkidx[2 * t + 1] = i2;
        g_tkw[2 * t] = v1 / sum;  g_tkw[2 * t + 1] = v2 / sum;
        g_argmax[t] = i1;
    }
}

// ---------------- deterministic per-expert compaction ----------------
__global__ void build_lists_kernel() {
    __shared__ int scnt[32][NEXP];
    __shared__ int choff[32][NEXP];
    __shared__ int eoff[NEXP];
    const int tid = threadIdx.x;
    const int e = tid & 7, ch = tid >> 3;   // 32 chunks x 8 experts = 256 threads
    const int t0 = ch * (TOKENS / 32);
    int c = 0;
    for (int t = t0; t < t0 + TOKENS / 32; t++) {
        if (g_tkidx[2 * t]     == e) c++;
        if (g_tkidx[2 * t + 1] == e) c++;
    }
    scnt[ch][e] = c;
    __syncthreads();
    if (tid < NEXP) {
        int s = 0;
        for (int j = 0; j < 32; j++) { choff[j][tid] = s; s += scnt[j][tid]; }
        g_cnt[tid] = s;
    }
    __syncthreads();
    if (tid == 0) {
        int s = 0;
        for (int j = 0; j < NEXP; j++) { eoff[j] = s; g_off[j] = s; s += g_cnt[j]; }
        g_off[NEXP] = s;
    }
    __syncthreads();
    int pos = eoff[e] + choff[ch][e];
    for (int t = t0; t < t0 + TOKENS / 32; t++) {
        #pragma unroll
        for (int k = 0; k < 2; k++)
            if (g_tkidx[2 * t + k] == e) {
                g_perm[pos] = t;
                g_wt[pos]   = g_tkw[2 * t + k];
                pos++;
            }
    }
}

// ---------------- aux loss (deterministic tree reduction) ----------------
__global__ void aux_kernel(float* __restrict__ out, int out_size) {
    __shared__ float sp[NEXP][256];
    __shared__ int   sc[NEXP][256];
    const int tid = threadIdx.x;
    float p[NEXP]; int cc[NEXP];
    #pragma unroll
    for (int e = 0; e < NEXP; e++) { p[e] = 0.f; cc[e] = 0; }
    for (int t = tid; t < TOKENS; t += 256) {
        #pragma unroll
        for (int e = 0; e < NEXP; e++) p[e] += g_probs[t * NEXP + e];
        cc[g_argmax[t]]++;
    }
    #pragma unroll
    for (int e = 0; e < NEXP; e++) { sp[e][tid] = p[e]; sc[e][tid] = cc[e]; }
    __syncthreads();
    for (int s = 128; s > 0; s >>= 1) {
        if (tid < s) {
            #pragma unroll
            for (int e = 0; e < NEXP; e++) {
                sp[e][tid] += sp[e][tid + s];
                sc[e][tid] += sc[e][tid + s];
            }
        }
        __syncthreads();
    }
    if (tid == 0 && out_size > TOKENS * D_MODEL) {
        float aux = 0.f;
        #pragma unroll
        for (int e = 0; e < NEXP; e++)
            aux += ((float)sc[e][0] / (float)TOKENS) * (sp[e][0] / (float)TOKENS);
        out[out_size - 1] = (float)NEXP * aux;
    }
}

// ---------------- grouped GEMM 1: h = gelu(X_e @ W1[e] + b1[e]) ----------------
// Tile 128x128, TK=16, 256 threads, 8x8 per thread via fma.rn.f32x2.
__global__ __launch_bounds__(256, 2)
void gemm1_kernel(const float* __restrict__ x,
                  const float* __restrict__ W1,
                  const float* __restrict__ b1) {
    const int e   = blockIdx.z;
    const int cnt = g_cnt[e];
    const int m0  = blockIdx.y * 128;
    if (m0 >= cnt) return;
    const int n0  = blockIdx.x * 128;
    const int off = g_off[e];
    const float* Bp = W1 + (size_t)e * D_MODEL * D_FF;

    __shared__ __align__(16) float As[16][132];
    __shared__ __align__(16) float Bs[16][128];

    const int tid = threadIdx.x;
    const int tr = tid >> 4;          // 0..15
    const int tc = tid & 15;          // 0..15

    const int ma = tid >> 2;          // 0..63
    const int kq = tid & 3;
    const int r0 = m0 + ma;
    const int r1 = r0 + 64;
    const bool v0 = r0 < cnt;
    const bool v1 = r1 < cnt;
    const float* pa0 = v0 ? (x + (size_t)g_perm[off + r0] * D_MODEL) : x;
    const float* pa1 = v1 ? (x + (size_t)g_perm[off + r1] * D_MODEL) : x;

    const int kb = tid >> 5;          // 0..7
    const int nb = (tid & 31) * 4;

    unsigned long long acc[8][4];
    #pragma unroll
    for (int i = 0; i < 8; i++)
        #pragma unroll
        for (int j = 0; j < 4; j++) acc[i][j] = 0ull;

    for (int k0 = 0; k0 < D_MODEL; k0 += 16) {
        float4 fa0 = v0 ? *(const float4*)(pa0 + k0 + kq * 4) : make_float4(0, 0, 0, 0);
        float4 fa1 = v1 ? *(const float4*)(pa1 + k0 + kq * 4) : make_float4(0, 0, 0, 0);
        float4 fb0 = *(const float4*)(Bp + (size_t)(k0 + kb) * D_FF + n0 + nb);
        float4 fb1 = *(const float4*)(Bp + (size_t)(k0 + kb + 8) * D_FF + n0 + nb);
        As[kq * 4 + 0][ma] = fa0.x;  As[kq * 4 + 1][ma] = fa0.y;
        As[kq * 4 + 2][ma] = fa0.z;  As[kq * 4 + 3][ma] = fa0.w;
        As[kq * 4 + 0][64 + ma] = fa1.x;  As[kq * 4 + 1][64 + ma] = fa1.y;
        As[kq * 4 + 2][64 + ma] = fa1.z;  As[kq * 4 + 3][64 + ma] = fa1.w;
        *(float4*)&Bs[kb][nb]     = fb0;
        *(float4*)&Bs[kb + 8][nb] = fb1;
        __syncthreads();
        #pragma unroll
        for (int k = 0; k < 16; k++) {
            float4 a0 = *(const float4*)&As[k][tr * 4];
            float4 a1 = *(const float4*)&As[k][64 + tr * 4];
            ulonglong2 b0 = *(const ulonglong2*)&Bs[k][tc * 4];
            ulonglong2 b1 = *(const ulonglong2*)&Bs[k][64 + tc * 4];
            float av[8] = {a0.x, a0.y, a0.z, a0.w, a1.x, a1.y, a1.z, a1.w};
            unsigned long long bv[4] = {b0.x, b0.y, b1.x, b1.y};
            #pragma unroll
            for (int r = 0; r < 8; r++) {
                unsigned long long a2 = pack2(av[r]);
                #pragma unroll
                for (int c = 0; c < 4; c++) fma2(acc[r][c], a2, bv[c]);
            }
        }
        __syncthreads();
    }
    #pragma unroll
    for (int r = 0; r < 8; r++) {
        int ml = (r < 4) ? (tr * 4 + r) : (64 + tr * 4 + (r - 4));
        int gm = m0 + ml;
        if (gm >= cnt) continue;
        size_t rowbase = (size_t)(off + gm) * D_FF;
        #pragma unroll
        for (int c = 0; c < 4; c++) {
            float2 u = unpack2(acc[r][c]);
            int col = (c < 2) ? (tc * 4 + c * 2) : (64 + tc * 4 + (c - 2) * 2);
            int n = n0 + col;
            float h0 = u.x + b1[e * D_FF + n];
            float h1 = u.y + b1[e * D_FF + n + 1];
            g_h[rowbase + n]     = gelu_exact(h0);
            g_h[rowbase + n + 1] = gelu_exact(h1);
        }
    }
}

// ---------------- grouped GEMM 2: out += w * (H_e @ W2[e] + b2[e]) ----------------
__global__ __launch_bounds__(256, 2)
void gemm2_kernel(const float* __restrict__ W2,
                  const float* __restrict__ b2,
                  float* __restrict__ out) {
    const int e   = blockIdx.z;
    const int cnt = g_cnt[e];
    const int m0  = blockIdx.y * 128;
    if (m0 >= cnt) return;
    const int n0  = blockIdx.x * 128;
    const int off = g_off[e];
    const float* Bp = W2 + (size_t)e * D_FF * D_MODEL;

    __shared__ __align__(16) float As[16][132];
    __shared__ __align__(16) float Bs[16][128];

    const int tid = threadIdx.x;
    const int tr = tid >> 4;
    const int tc = tid & 15;

    const int ma = tid >> 2;
    const int kq = tid & 3;
    const int r0 = m0 + ma;
    const int r1 = r0 + 64;
    const bool v0 = r0 < cnt;
    const bool v1 = r1 < cnt;
    const float* pa0 = v0 ? (g_h + (size_t)(off + r0) * D_FF) : g_h;
    const float* pa1 = v1 ? (g_h + (size_t)(off + r1) * D_FF) : g_h;

    const int kb = tid >> 5;
    const int nb = (tid & 31) * 4;

    unsigned long long acc[8][4];
    #pragma unroll
    for (int i = 0; i < 8; i++)
        #pragma unroll
        for (int j = 0; j < 4; j++) acc[i][j] = 0ull;

    for (int k0 = 0; k0 < D_FF; k0 += 16) {
        float4 fa0 = v0 ? *(const float4*)(pa0 + k0 + kq * 4) : make_float4(0, 0, 0, 0);
        float4 fa1 = v1 ? *(const float4*)(pa1 + k0 + kq * 4) : make_float4(0, 0, 0, 0);
        float4 fb0 = *(const float4*)(Bp + (size_t)(k0 + kb) * D_MODEL + n0 + nb);
        float4 fb1 = *(const float4*)(Bp + (size_t)(k0 + kb + 8) * D_MODEL + n0 + nb);
        As[kq * 4 + 0][ma] = fa0.x;  As[kq * 4 + 1][ma] = fa0.y;
        As[kq * 4 + 2][ma] = fa0.z;  As[kq * 4 + 3][ma] = fa0.w;
        As[kq * 4 + 0][64 + ma] = fa1.x;  As[kq * 4 + 1][64 + ma] = fa1.y;
        As[kq * 4 + 2][64 + ma] = fa1.z;  As[kq * 4 + 3][64 + ma] = fa1.w;
        *(float4*)&Bs[kb][nb]     = fb0;
        *(float4*)&Bs[kb + 8][nb] = fb1;
        __syncthreads();
        #pragma unroll
        for (int k = 0; k < 16; k++) {
            float4 a0 = *(const float4*)&As[k][tr * 4];
            float4 a1 = *(const float4*)&As[k][64 + tr * 4];
            ulonglong2 b0 = *(const ulonglong2*)&Bs[k][tc * 4];
            ulonglong2 b1 = *(const ulonglong2*)&Bs[k][64 + tc * 4];
            float av[8] = {a0.x, a0.y, a0.z, a0.w, a1.x, a1.y, a1.z, a1.w};
            unsigned long long bv[4] = {b0.x, b0.y, b1.x, b1.y};
            #pragma unroll
            for (int r = 0; r < 8; r++) {
                unsigned long long a2 = pack2(av[r]);
                #pragma unroll
                for (int c = 0; c < 4; c++) fma2(acc[r][c], a2, bv[c]);
            }
        }
        __syncthreads();
    }
    #pragma unroll
    for (int r = 0; r < 8; r++) {
        int ml = (r < 4) ? (tr * 4 + r) : (64 + tr * 4 + (r - 4));
        int gm = m0 + ml;
        if (gm >= cnt) continue;
        int slot = off + gm;
        int tok = g_perm[slot];
        float w = g_wt[slot];
        #pragma unroll
        for (int c = 0; c < 4; c++) {
            float2 u = unpack2(acc[r][c]);
            int col = (c < 2) ? (tc * 4 + c * 2) : (64 + tc * 4 + (c - 2) * 2);
            int n = n0 + col;
            float y0 = u.x + b2[e * D_MODEL + n];
            float y1 = u.y + b2[e * D_MODEL + n + 1];
            atomicAdd(&out[(size_t)tok * D_MODEL + n],     w * y0);
            atomicAdd(&out[(size_t)tok * D_MODEL + n + 1], w * y1);
        }
    }
}

// ---------------- launch ----------------
extern "C" void kernel_launch(void* const* d_in, const int* in_sizes, int n_in,
                              void* d_out, int out_size) {
    const float* x  = (const float*)d_in[0];
    const float* Wr = (const float*)d_in[1];
    const float* br = (const float*)d_in[2];
    const float* W1 = (const float*)d_in[3];
    const float* b1 = (const float*)d_in[4];
    const float* W2 = (const float*)d_in[5];
    const float* b2 = (const float*)d_in[6];
    float* out = (float*)d_out;

    cudaMemsetAsync(out, 0, (size_t)TOKENS * D_MODEL * sizeof(float), 0);
    router_kernel<<<TOKENS, 128>>>(x, Wr, br);
    build_lists_kernel<<<1, 256>>>();
    aux_kernel<<<1, 256>>>(out, out_size);
    gemm1_kernel<<<dim3(D_FF / 128, NASSIGN / 128, NEXP), 256>>>(x, W1, b1);
    gemm2_kernel<<<dim3(D_MODEL / 128, NASSIGN / 128, NEXP), 256>>>(W2, b2, out);
}

// round 4
// speedup vs baseline: 1.5114x; 1.5114x over previous
#include <cuda_runtime.h>
#include <cuda_bf16.h>
#include <cmath>
#include <cstdint>

#define D_MODEL 1024
#define D_FF    4096
#define NEXP    8
#define TOKENS  4096            // B*S = 2*2048
#define NASSIGN (TOKENS * 2)    // top-k = 2

// ---------------- device scratch (no allocations allowed) ----------------
__device__ int   g_cnt[NEXP];
__device__ int   g_off[NEXP + 1];
__device__ int   g_perm[NASSIGN];
__device__ float g_wt[NASSIGN];
__device__ float g_probs[TOKENS * NEXP];
__device__ int   g_argmax[TOKENS];
__device__ int   g_tkidx[TOKENS * 2];
__device__ float g_tkw[TOKENS * 2];
__device__ __align__(16) float g_h[(size_t)NASSIGN * D_FF];  // 134 MB intermediate (fp32)

// ---------------- smem layout (bf16, padded, no swizzle) ----------------
// A tile: 128 rows x 32 k, rows padded to 40 elems (80 B, 16B-aligned)
// B tile: 32 k-rows x 128 n, rows padded to 136 elems (272 B, 16B-aligned)
#define AH_OFF 0
#define AL_OFF 10240
#define BH_OFF 20480
#define BL_OFF 29184
#define STAGE_BYTES 37888
#define SMEM_BYTES  (2 * STAGE_BYTES)   // 75776

// ---------------- PTX helpers (baseline PTX only, no sm_103a features) ----
__device__ __forceinline__ uint32_t smem_u32(const void* p) {
    uint32_t a;
    asm("{ .reg .u64 t; cvta.to.shared.u64 t, %1; cvt.u32.u64 %0, t; }"
        : "=r"(a) : "l"(p));
    return a;
}
__device__ __forceinline__ void ldsm4(uint32_t* r, uint32_t addr) {
    asm volatile("ldmatrix.sync.aligned.m8n8.x4.shared.b16 {%0,%1,%2,%3}, [%4];"
        : "=r"(r[0]), "=r"(r[1]), "=r"(r[2]), "=r"(r[3]) : "r"(addr));
}
__device__ __forceinline__ void ldsm4t(uint32_t* r, uint32_t addr) {
    asm volatile("ldmatrix.sync.aligned.m8n8.x4.trans.shared.b16 {%0,%1,%2,%3}, [%4];"
        : "=r"(r[0]), "=r"(r[1]), "=r"(r[2]), "=r"(r[3]) : "r"(addr));
}
__device__ __forceinline__ void mma16816(float* c, const uint32_t* a,
                                         uint32_t b0, uint32_t b1) {
    asm volatile("mma.sync.aligned.m16n8k16.row.col.f32.bf16.bf16.f32 "
        "{%0,%1,%2,%3}, {%4,%5,%6,%7}, {%8,%9}, {%0,%1,%2,%3};"
        : "+f"(c[0]), "+f"(c[1]), "+f"(c[2]), "+f"(c[3])
        : "r"(a[0]), "r"(a[1]), "r"(a[2]), "r"(a[3]), "r"(b0), "r"(b1));
}
// fp32x4 -> bf16 hi/lo split, 8-byte stores into two tiles
__device__ __forceinline__ void split8(char* hi, char* lo, float4 v) {
    __nv_bfloat16 h0 = __float2bfloat16_rn(v.x);
    __nv_bfloat16 h1 = __float2bfloat16_rn(v.y);
    __nv_bfloat16 h2 = __float2bfloat16_rn(v.z);
    __nv_bfloat16 h3 = __float2bfloat16_rn(v.w);
    __nv_bfloat16 l0 = __float2bfloat16_rn(v.x - __bfloat162float(h0));
    __nv_bfloat16 l1 = __float2bfloat16_rn(v.y - __bfloat162float(h1));
    __nv_bfloat16 l2 = __float2bfloat16_rn(v.z - __bfloat162float(h2));
    __nv_bfloat16 l3 = __float2bfloat16_rn(v.w - __bfloat162float(h3));
    uint2 H, L;
    H.x = (uint32_t)__bfloat16_as_ushort(h0) | ((uint32_t)__bfloat16_as_ushort(h1) << 16);
    H.y = (uint32_t)__bfloat16_as_ushort(h2) | ((uint32_t)__bfloat16_as_ushort(h3) << 16);
    L.x = (uint32_t)__bfloat16_as_ushort(l0) | ((uint32_t)__bfloat16_as_ushort(l1) << 16);
    L.y = (uint32_t)__bfloat16_as_ushort(l2) | ((uint32_t)__bfloat16_as_ushort(l3) << 16);
    *(uint2*)hi = H;
    *(uint2*)lo = L;
}
__device__ __forceinline__ float gelu_exact(float v) {
    return 0.5f * v * (1.0f + erff(v * 0.70710678118654752f));
}

// store one chunk's A+B tiles (register data) into a smem stage
__device__ __forceinline__ void store_tiles(char* st, int am, int akh, int bkr, int bn,
                                            const float4* ra, const float4* rb) {
    #pragma unroll
    for (int j = 0; j < 4; j++) {
        int o = (am * 40 + akh + j * 4) * 2;
        split8(st + AH_OFF + o, st + AL_OFF + o, ra[j]);
    }
    #pragma unroll
    for (int j = 0; j < 4; j++) {
        int o = (bkr * 136 + bn + j * 4) * 2;
        split8(st + BH_OFF + o, st + BL_OFF + o, rb[j]);
    }
}

// compute one 32-k chunk: 3-term bf16 split, warp tile 32x64
__device__ __forceinline__ void compute_chunk(uint32_t sbS, int wm, int wn, int lid,
                                              float (&acc)[2][8][4]) {
    const int lr = lid & 15;
    const int lc = (lid >> 4) * 8;
    #pragma unroll
    for (int ks = 0; ks < 2; ks++) {
        uint32_t ah[2][4], al[2][4];
        #pragma unroll
        for (int mi = 0; mi < 2; mi++) {
            uint32_t ra = sbS + AH_OFF +
                (uint32_t)(((wm * 32 + mi * 16 + lr) * 40 + ks * 16 + lc) * 2);
            ldsm4(ah[mi], ra);
            ldsm4(al[mi], ra + (AL_OFF - AH_OFF));
        }
        #pragma unroll
        for (int nq = 0; nq < 4; nq++) {
            uint32_t bh[4], bl[4];
            uint32_t rb = sbS + BH_OFF +
                (uint32_t)(((ks * 16 + lr) * 136 + wn * 64 + nq * 16 + lc) * 2);
            ldsm4t(bh, rb);
            ldsm4t(bl, rb + (BL_OFF - BH_OFF));
            #pragma unroll
            for (int mi = 0; mi < 2; mi++) {
                mma16816(acc[mi][nq * 2],     ah[mi], bh[0], bh[1]);
                mma16816(acc[mi][nq * 2 + 1], ah[mi], bh[2], bh[3]);
                mma16816(acc[mi][nq * 2],     ah[mi], bl[0], bl[1]);
                mma16816(acc[mi][nq * 2 + 1], ah[mi], bl[2], bl[3]);
                mma16816(acc[mi][nq * 2],     al[mi], bh[0], bh[1]);
                mma16816(acc[mi][nq * 2 + 1], al[mi], bh[2], bh[3]);
            }
        }
    }
}

// ---------------- router ----------------
__global__ void router_kernel(const float* __restrict__ x,
                              const float* __restrict__ Wr,
                              const float* __restrict__ br) {
    const int t = blockIdx.x;
    const float* xr = x + (size_t)t * D_MODEL;
    float acc[NEXP];
    #pragma unroll
    for (int e = 0; e < NEXP; e++) acc[e] = 0.f;
    for (int d = threadIdx.x; d < D_MODEL; d += 128) {
        float xv = xr[d];
        const float* w = Wr + d * NEXP;
        #pragma unroll
        for (int e = 0; e < NEXP; e++) acc[e] = fmaf(xv, w[e], acc[e]);
    }
    __shared__ float red[NEXP][128];
    #pragma unroll
    for (int e = 0; e < NEXP; e++) red[e][threadIdx.x] = acc[e];
    __syncthreads();
    for (int s = 64; s > 0; s >>= 1) {
        if (threadIdx.x < s) {
            #pragma unroll
            for (int e = 0; e < NEXP; e++)
                red[e][threadIdx.x] += red[e][threadIdx.x + s];
        }
        __syncthreads();
    }
    if (threadIdx.x == 0) {
        float lg[NEXP], p[NEXP];
        float mx = -1e30f;
        #pragma unroll
        for (int e = 0; e < NEXP; e++) { lg[e] = red[e][0] + br[e]; mx = fmaxf(mx, lg[e]); }
        float s = 0.f;
        #pragma unroll
        for (int e = 0; e < NEXP; e++) { p[e] = expf(lg[e] - mx); s += p[e]; }
        float inv = 1.f / s;
        #pragma unroll
        for (int e = 0; e < NEXP; e++) { p[e] *= inv; g_probs[t * NEXP + e] = p[e]; }
        int i1 = 0;
        #pragma unroll
        for (int e = 1; e < NEXP; e++) if (p[e] > p[i1]) i1 = e;
        int i2 = (i1 == 0) ? 1 : 0;
        #pragma unroll
        for (int e = 0; e < NEXP; e++) if (e != i1 && p[e] > p[i2]) i2 = e;
        float v1 = p[i1], v2 = p[i2];
        float sum = fmaxf(v1 + v2, 1e-9f);
        g_tkidx[2 * t] = i1;  g_tkidx[2 * t + 1] = i2;
        g_tkw[2 * t] = v1 / sum;  g_tkw[2 * t + 1] = v2 / sum;
        g_argmax[t] = i1;
    }
}

// ---------------- deterministic per-expert compaction ----------------
__global__ void build_lists_kernel() {
    __shared__ int scnt[32][NEXP];
    __shared__ int choff[32][NEXP];
    __shared__ int eoff[NEXP];
    const int tid = threadIdx.x;
    const int e = tid & 7, ch = tid >> 3;
    const int t0 = ch * (TOKENS / 32);
    int c = 0;
    for (int t = t0; t < t0 + TOKENS / 32; t++) {
        if (g_tkidx[2 * t]     == e) c++;
        if (g_tkidx[2 * t + 1] == e) c++;
    }
    scnt[ch][e] = c;
    __syncthreads();
    if (tid < NEXP) {
        int s = 0;
        for (int j = 0; j < 32; j++) { choff[j][tid] = s; s += scnt[j][tid]; }
        g_cnt[tid] = s;
    }
    __syncthreads();
    if (tid == 0) {
        int s = 0;
        for (int j = 0; j < NEXP; j++) { eoff[j] = s; g_off[j] = s; s += g_cnt[j]; }
        g_off[NEXP] = s;
    }
    __syncthreads();
    int pos = eoff[e] + choff[ch][e];
    for (int t = t0; t < t0 + TOKENS / 32; t++) {
        #pragma unroll
        for (int k = 0; k < 2; k++)
            if (g_tkidx[2 * t + k] == e) {
                g_perm[pos] = t;
                g_wt[pos]   = g_tkw[2 * t + k];
                pos++;
            }
    }
}

// ---------------- aux loss ----------------
__global__ void aux_kernel(float* __restrict__ out, int out_size) {
    __shared__ float sp[NEXP][256];
    __shared__ int   sc[NEXP][256];
    const int tid = threadIdx.x;
    float p[NEXP]; int cc[NEXP];
    #pragma unroll
    for (int e = 0; e < NEXP; e++) { p[e] = 0.f; cc[e] = 0; }
    for (int t = tid; t < TOKENS; t += 256) {
        #pragma unroll
        for (int e = 0; e < NEXP; e++) p[e] += g_probs[t * NEXP + e];
        cc[g_argmax[t]]++;
    }
    #pragma unroll
    for (int e = 0; e < NEXP; e++) { sp[e][tid] = p[e]; sc[e][tid] = cc[e]; }
    __syncthreads();
    for (int s = 128; s > 0; s >>= 1) {
        if (tid < s) {
            #pragma unroll
            for (int e = 0; e < NEXP; e++) {
                sp[e][tid] += sp[e][tid + s];
                sc[e][tid] += sc[e][tid + s];
            }
        }
        __syncthreads();
    }
    if (tid == 0 && out_size > TOKENS * D_MODEL) {
        float aux = 0.f;
        #pragma unroll
        for (int e = 0; e < NEXP; e++)
            aux += ((float)sc[e][0] / (float)TOKENS) * (sp[e][0] / (float)TOKENS);
        out[out_size - 1] = (float)NEXP * aux;
    }
}

// ---------------- GEMM1 (mma.sync bf16 3-term): h = gelu(X_e @ W1[e] + b1) ---
__global__ __launch_bounds__(256, 1)
void gemm1_mma(const float* __restrict__ x,
               const float* __restrict__ W1,
               const float* __restrict__ b1) {
    const int e   = blockIdx.z;
    const int cnt = g_cnt[e];
    const int m0  = blockIdx.y * 128;
    if (m0 >= cnt) return;
    const int n0  = blockIdx.x * 128;
    const int off = g_off[e];
    const float* W1e = W1 + (size_t)e * D_MODEL * D_FF;

    extern __shared__ __align__(128) char smem[];
    const uint32_t sb = smem_u32(smem);
    const int tid = threadIdx.x;
    const int lid = tid & 31;
    const int wid = tid >> 5;
    const int wm = wid >> 1, wn = wid & 1;

    // producer mapping
    const int am  = tid >> 1;            // 0..127 (tile row)
    const int akh = (tid & 1) * 16;      // k half
    const int bkr = tid >> 3;            // 0..31 (k row)
    const int bn  = (tid & 7) * 16;      // n base
    const int tok = (m0 + am < cnt) ? g_perm[off + m0 + am] : g_perm[off];
    const float* aptr = x + (size_t)tok * D_MODEL + akh;
    const float* bptr = W1e + (size_t)bkr * D_FF + n0 + bn;

    float acc[2][8][4];
    #pragma unroll
    for (int i = 0; i < 2; i++)
        #pragma unroll
        for (int j = 0; j < 8; j++)
            #pragma unroll
            for (int k = 0; k < 4; k++) acc[i][j][k] = 0.f;

    float4 ra[4], rb[4];
    #pragma unroll
    for (int j = 0; j < 4; j++) ra[j] = *(const float4*)(aptr + j * 4);
    #pragma unroll
    for (int j = 0; j < 4; j++) rb[j] = *(const float4*)(bptr + j * 4);
    store_tiles(smem, am, akh, bkr, bn, ra, rb);
    __syncthreads();

    const int NC = D_MODEL / 32;   // 32
    for (int c = 0; c < NC; c++) {
        if (c + 1 < NC) {
            #pragma unroll
            for (int j = 0; j < 4; j++)
                ra[j] = *(const float4*)(aptr + (c + 1) * 32 + j * 4);
            #pragma unroll
            for (int j = 0; j < 4; j++)
                rb[j] = *(const float4*)(bptr + (size_t)(c + 1) * 32 * D_FF + j * 4);
        }
        compute_chunk(sb + (uint32_t)((c & 1) * STAGE_BYTES), wm, wn, lid, acc);
        if (c + 1 < NC) {
            store_tiles(smem + ((c + 1) & 1) * STAGE_BYTES, am, akh, bkr, bn, ra, rb);
            __syncthreads();
        }
    }

    // epilogue: bias + exact gelu, float2 stores
    const int lgrp  = lid >> 2;
    const int lquad = (lid & 3) * 2;
    #pragma unroll
    for (int mi = 0; mi < 2; mi++) {
        const int r0 = m0 + wm * 32 + mi * 16 + lgrp;
        const int r1 = r0 + 8;
        #pragma unroll
        for (int n8 = 0; n8 < 8; n8++) {
            const int colg = n0 + wn * 64 + n8 * 8 + lquad;
            float2 bb = *(const float2*)(b1 + e * D_FF + colg);
            const float* a4 = acc[mi][n8];
            if (r0 < cnt) {
                float2 v;
                v.x = gelu_exact(a4[0] + bb.x);
                v.y = gelu_exact(a4[1] + bb.y);
                *(float2*)(g_h + (size_t)(off + r0) * D_FF + colg) = v;
            }
            if (r1 < cnt) {
                float2 v;
                v.x = gelu_exact(a4[2] + bb.x);
                v.y = gelu_exact(a4[3] + bb.y);
                *(float2*)(g_h + (size_t)(off + r1) * D_FF + colg) = v;
            }
        }
    }
}

// ---------------- GEMM2 (mma.sync bf16 3-term): out += w*(H_e @ W2[e] + b2) --
__global__ __launch_bounds__(256, 1)
void gemm2_mma(const float* __restrict__ W2,
               const float* __restrict__ b2,
               float* __restrict__ out) {
    const int e   = blockIdx.z;
    const int cnt = g_cnt[e];
    const int m0  = blockIdx.y * 128;
    if (m0 >= cnt) return;
    const int n0  = blockIdx.x * 128;
    const int off = g_off[e];
    const float* W2e = W2 + (size_t)e * D_FF * D_MODEL;

    extern __shared__ __align__(128) char smem[];
    const uint32_t sb = smem_u32(smem);
    const int tid = threadIdx.x;
    const int lid = tid & 31;
    const int wid = tid >> 5;
    const int wm = wid >> 1, wn = wid & 1;

    const int am  = tid >> 1;
    const int akh = (tid & 1) * 16;
    const int bkr = tid >> 3;
    const int bn  = (tid & 7) * 16;
    const int rowi = (m0 + am < cnt) ? (off + m0 + am) : off;
    const float* aptr = g_h + (size_t)rowi * D_FF + akh;
    const float* bptr = W2e + (size_t)bkr * D_MODEL + n0 + bn;

    float acc[2][8][4];
    #pragma unroll
    for (int i = 0; i < 2; i++)
        #pragma unroll
        for (int j = 0; j < 8; j++)
            #pragma unroll
            for (int k = 0; k < 4; k++) acc[i][j][k] = 0.f;

    float4 ra[4], rb[4];
    #pragma unroll
    for (int j = 0; j < 4; j++) ra[j] = *(const float4*)(aptr + j * 4);
    #pragma unroll
    for (int j = 0; j < 4; j++) rb[j] = *(const float4*)(bptr + j * 4);
    store_tiles(smem, am, akh, bkr, bn, ra, rb);
    __syncthreads();

    const int NC = D_FF / 32;   // 128
    for (int c = 0; c < NC; c++) {
        if (c + 1 < NC) {
            #pragma unroll
            for (int j = 0; j < 4; j++)
                ra[j] = *(const float4*)(aptr + (c + 1) * 32 + j * 4);
            #pragma unroll
            for (int j = 0; j < 4; j++)
                rb[j] = *(const float4*)(bptr + (size_t)(c + 1) * 32 * D_MODEL + j * 4);
        }
        compute_chunk(sb + (uint32_t)((c & 1) * STAGE_BYTES), wm, wn, lid, acc);
        if (c + 1 < NC) {
            store_tiles(smem + ((c + 1) & 1) * STAGE_BYTES, am, akh, bkr, bn, ra, rb);
            __syncthreads();
        }
    }

    // epilogue: bias, gate-weight scale, vector atomic accumulate
    const int lgrp  = lid >> 2;
    const int lquad = (lid & 3) * 2;
    #pragma unroll
    for (int mi = 0; mi < 2; mi++) {
        const int r0 = m0 + wm * 32 + mi * 16 + lgrp;
        const int r1 = r0 + 8;
        const bool v0 = r0 < cnt, v1 = r1 < cnt;
        const int  s0 = v0 ? (off + r0) : off;
        const int  s1 = v1 ? (off + r1) : off;
        const int  t0 = g_perm[s0], t1 = g_perm[s1];
        const float w0 = v0 ? g_wt[s0] : 0.f;
        const float w1 = v1 ? g_wt[s1] : 0.f;
        #pragma unroll
        for (int n8 = 0; n8 < 8; n8++) {
            const int colg = n0 + wn * 64 + n8 * 8 + lquad;
            float2 bb = *(const float2*)(b2 + e * D_MODEL + colg);
            const float* a4 = acc[mi][n8];
            if (v0) {
                float2 v = make_float2(w0 * (a4[0] + bb.x), w0 * (a4[1] + bb.y));
                atomicAdd((float2*)(out + (size_t)t0 * D_MODEL + colg), v);
            }
            if (v1) {
                float2 v = make_float2(w1 * (a4[2] + bb.x), w1 * (a4[3] + bb.y));
                atomicAdd((float2*)(out + (size_t)t1 * D_MODEL + colg), v);
            }
        }
    }
}

// ---------------- launch ----------------
extern "C" void kernel_launch(void* const* d_in, const int* in_sizes, int n_in,
                              void* d_out, int out_size) {
    const float* x  = (const float*)d_in[0];
    const float* Wr = (const float*)d_in[1];
    const float* br = (const float*)d_in[2];
    const float* W1 = (const float*)d_in[3];
    const float* b1 = (const float*)d_in[4];
    const float* W2 = (const float*)d_in[5];
    const float* b2 = (const float*)d_in[6];
    float* out = (float*)d_out;

    cudaFuncSetAttribute(gemm1_mma, cudaFuncAttributeMaxDynamicSharedMemorySize, SMEM_BYTES);
    cudaFuncSetAttribute(gemm2_mma, cudaFuncAttributeMaxDynamicSharedMemorySize, SMEM_BYTES);

    cudaMemsetAsync(out, 0, (size_t)TOKENS * D_MODEL * sizeof(float), 0);
    router_kernel<<<TOKENS, 128>>>(x, Wr, br);
    build_lists_kernel<<<1, 256>>>();
    aux_kernel<<<1, 256>>>(out, out_size);
    gemm1_mma<<<dim3(D_FF / 128, TOKENS / 128, NEXP), 256, SMEM_BYTES>>>(x, W1, b1);
    gemm2_mma<<<dim3(D_MODEL / 128, TOKENS / 128, NEXP), 256, SMEM_BYTES>>>(W2, b2, out);
}